// round 1
// baseline (speedup 1.0000x reference)
#include <cuda_runtime.h>

#define LN 1024
#define BATCH 64
#define THREADS 256
#define NCG 16                    // column groups per CTA
#define NRG 16                    // row groups per CTA
#define RPT 4                     // rows per thread
#define ROWS_PER_CTA (NRG * RPT)  // 64
#define TILES (LN / ROWS_PER_CTA) // 16
#define COLS_PER_THREAD (LN / NCG)// 64

__device__ float g_batch_acc[BATCH];

__global__ void zero_kernel() {
    if (threadIdx.x < BATCH) g_batch_acc[threadIdx.x] = 0.0f;
}

__device__ __forceinline__ float fast_sqrt(float a) {
    float r;
    asm("sqrt.approx.f32 %0, %1;" : "=f"(r) : "f"(a));
    return r;
}

__global__ __launch_bounds__(THREADS, 4)
void pair_kernel(const float* __restrict__ x, const float* __restrict__ y) {
    const int b    = blockIdx.x;   // batch
    const int tile = blockIdx.y;   // row tile

    __shared__ float4 xs[LN];      // (x0,x1,x2, sq_x)
    __shared__ float4 ys[LN];      // (y0,y1,y2, sq_y)
    __shared__ float  msk[LN];     // 1.0 if y-row observed
    __shared__ float  wsum[THREADS / 32];

    // ---- fill shared: gather batch b from [L, B, 3] layout ----
    for (int l = threadIdx.x; l < LN; l += THREADS) {
        int base = (l * BATCH + b) * 3;
        float x0 = x[base + 0], x1 = x[base + 1], x2 = x[base + 2];
        float y0 = y[base + 0], y1 = y[base + 1], y2 = y[base + 2];
        float sqx = fmaf(x2, x2, fmaf(x1, x1, x0 * x0));
        float sqy = fmaf(y2, y2, fmaf(y1, y1, y0 * y0));
        xs[l] = make_float4(x0, x1, x2, sqx);
        ys[l] = make_float4(y0, y1, y2, sqy);
        msk[l] = ((y0 + y1 + y2) != 0.0f) ? 1.0f : 0.0f;
    }
    __syncthreads();

    const int cg = threadIdx.x & (NCG - 1);
    const int rg = threadIdx.x >> 4;
    const int row0 = tile * ROWS_PER_CTA + rg * RPT;

    // ---- row data into registers ----
    float ax0[RPT], ax1[RPT], ax2[RPT], cx[RPT];
    float ay0[RPT], ay1[RPT], ay2[RPT], cy[RPT];
    float rmask[RPT];
    float anyrow = 0.0f;
#pragma unroll
    for (int r = 0; r < RPT; r++) {
        float4 px = xs[row0 + r];
        float4 py = ys[row0 + r];
        ax0[r] = -2.0f * px.x; ax1[r] = -2.0f * px.y; ax2[r] = -2.0f * px.z; cx[r] = px.w;
        ay0[r] = -2.0f * py.x; ay1[r] = -2.0f * py.y; ay2[r] = -2.0f * py.z; cy[r] = py.w;
        rmask[r] = msk[row0 + r];
        anyrow += rmask[r];
    }

    float acc[RPT] = {0.0f, 0.0f, 0.0f, 0.0f};

    if (anyrow != 0.0f) {
#pragma unroll 4
        for (int jj = 0; jj < COLS_PER_THREAD; jj++) {
            int j = cg + jj * NCG;          // interleaved -> conflict-free LDS.128
            float4 px = xs[j];
            float4 py = ys[j];
            float mj  = msk[j];
#pragma unroll
            for (int r = 0; r < RPT; r++) {
                float d2x = fmaf(ax2[r], px.z,
                            fmaf(ax1[r], px.y,
                            fmaf(ax0[r], px.x, cx[r] + px.w)));
                float d2y = fmaf(ay2[r], py.z,
                            fmaf(ay1[r], py.y,
                            fmaf(ay0[r], py.x, cy[r] + py.w)));
                d2x = fmaxf(d2x, 0.0f);
                d2y = fmaxf(d2y, 0.0f);
                float dx = fast_sqrt(d2x);
                float dy = fast_sqrt(d2y);
                float diff = (dy - dx) * mj;
                acc[r] = fmaf(diff, diff, acc[r]);
            }
        }
    }

    float tsum = 0.0f;
#pragma unroll
    for (int r = 0; r < RPT; r++) tsum = fmaf(acc[r], rmask[r], tsum);

    // ---- block reduce ----
#pragma unroll
    for (int o = 16; o > 0; o >>= 1)
        tsum += __shfl_down_sync(0xffffffffu, tsum, o);
    if ((threadIdx.x & 31) == 0) wsum[threadIdx.x >> 5] = tsum;
    __syncthreads();
    if (threadIdx.x < 8) {
        float s = wsum[threadIdx.x];
#pragma unroll
        for (int o = 4; o > 0; o >>= 1)
            s += __shfl_down_sync(0xffu, s, o);
        if (threadIdx.x == 0) atomicAdd(&g_batch_acc[b], s);
    }
}

__global__ void final_kernel(float* __restrict__ out) {
    if (threadIdx.x == 0) {
        float s = 0.0f;
        for (int i = 0; i < BATCH; i++) s += sqrtf(g_batch_acc[i]);
        const float denom = sqrtf((float)((double)LN * LN * 0.5 - (double)LN));
        out[0] = s / denom / (float)BATCH;
    }
}

extern "C" void kernel_launch(void* const* d_in, const int* in_sizes, int n_in,
                              void* d_out, int out_size) {
    const float* x = (const float*)d_in[0];
    const float* y = (const float*)d_in[1];
    float* out = (float*)d_out;
    (void)in_sizes; (void)n_in; (void)out_size;

    zero_kernel<<<1, 64>>>();
    dim3 grid(BATCH, TILES);
    pair_kernel<<<grid, THREADS>>>(x, y);
    final_kernel<<<1, 32>>>(out);
}

// round 3
// speedup vs baseline: 1.4763x; 1.4763x over previous
#include <cuda_runtime.h>

#define LN 1024
#define BATCH 64
#define THREADS 256
#define NCG 16
#define RPT 4
#define ROWS_PER_CTA 64
#define TILES (LN / ROWS_PER_CTA)

typedef unsigned long long u64;

// Scratch (device globals; no runtime allocation).
__device__ ulonglong2 g_colA[BATCH][LN];  // ( pack(x0,y0), pack(x1,y1) )
__device__ ulonglong2 g_colB[BATCH][LN];  // ( pack(x2,y2), pack(sqx,sqy) )
__device__ u64   g_hdrS[BATCH][4];        // S0, S1, S2, SQ   (packed x/y sums over valid)
__device__ int   g_nv[BATCH];
__device__ float g_part[BATCH * TILES];

// ---------- f32x2 helpers ----------
__device__ __forceinline__ u64 fma2(u64 a, u64 b, u64 c) {
    u64 d; asm("fma.rn.f32x2 %0, %1, %2, %3;" : "=l"(d) : "l"(a), "l"(b), "l"(c)); return d;
}
__device__ __forceinline__ u64 add2(u64 a, u64 b) {
    u64 d; asm("add.rn.f32x2 %0, %1, %2;" : "=l"(d) : "l"(a), "l"(b)); return d;
}
__device__ __forceinline__ u64 mul2(u64 a, u64 b) {
    u64 d; asm("mul.rn.f32x2 %0, %1, %2;" : "=l"(d) : "l"(a), "l"(b)); return d;
}
__device__ __forceinline__ u64 pack2(float lo, float hi) {
    u64 d; asm("mov.b64 %0, {%1, %2};" : "=l"(d) : "f"(lo), "f"(hi)); return d;
}
__device__ __forceinline__ float2 unpack2(u64 a) {
    float lo, hi; asm("mov.b64 {%0, %1}, %2;" : "=f"(lo), "=f"(hi) : "l"(a));
    return make_float2(lo, hi);
}
__device__ __forceinline__ float fast_sqrt(float a) {
    float r; asm("sqrt.approx.f32 %0, %1;" : "=f"(r) : "f"(a)); return r;
}

#define NEG2_PACKED 0xC0000000C0000000ULL  // (-2.0f, -2.0f)

// ---------- pre-kernel: per-batch compaction + sums ----------
__global__ __launch_bounds__(THREADS)
void pre_kernel(const float* __restrict__ x, const float* __restrict__ y) {
    const int b = blockIdx.x, tid = threadIdx.x;
    const int warp = tid >> 5, lane = tid & 31;

    __shared__ int   s_wcnt[8];
    __shared__ int   s_wbase[8];
    __shared__ int   s_nv;
    __shared__ float s_red[8][8];

    float X[4][3], Y[4][3], SQX[4], SQY[4];
    int m[4], cnt = 0;
#pragma unroll
    for (int i = 0; i < 4; i++) {
        int l = tid * 4 + i;
        int base = (l * BATCH + b) * 3;
        X[i][0] = x[base]; X[i][1] = x[base + 1]; X[i][2] = x[base + 2];
        Y[i][0] = y[base]; Y[i][1] = y[base + 1]; Y[i][2] = y[base + 2];
        SQX[i] = fmaf(X[i][2], X[i][2], fmaf(X[i][1], X[i][1], X[i][0] * X[i][0]));
        SQY[i] = fmaf(Y[i][2], Y[i][2], fmaf(Y[i][1], Y[i][1], Y[i][0] * Y[i][0]));
        m[i] = ((Y[i][0] + Y[i][1] + Y[i][2]) != 0.0f) ? 1 : 0;
        cnt += m[i];
    }

    // warp inclusive scan of counts (deterministic)
    int inc = cnt;
#pragma unroll
    for (int o = 1; o < 32; o <<= 1) {
        int v = __shfl_up_sync(0xffffffffu, inc, o);
        if (lane >= o) inc += v;
    }
    if (lane == 31) s_wcnt[warp] = inc;

    // masked partial sums: Sx0,Sy0,Sx1,Sy1,Sx2,Sy2,S1x,S1y
    float s[8] = {0, 0, 0, 0, 0, 0, 0, 0};
#pragma unroll
    for (int i = 0; i < 4; i++) {
        if (m[i]) {
            s[0] += X[i][0]; s[1] += Y[i][0];
            s[2] += X[i][1]; s[3] += Y[i][1];
            s[4] += X[i][2]; s[5] += Y[i][2];
            s[6] += SQX[i];  s[7] += SQY[i];
        }
    }
#pragma unroll
    for (int k = 0; k < 8; k++)
#pragma unroll
        for (int o = 16; o > 0; o >>= 1)
            s[k] += __shfl_down_sync(0xffffffffu, s[k], o);
    if (lane == 0)
#pragma unroll
        for (int k = 0; k < 8; k++) s_red[warp][k] = s[k];
    __syncthreads();

    if (tid == 0) {
        int acc = 0;
        for (int w = 0; w < 8; w++) { s_wbase[w] = acc; acc += s_wcnt[w]; }
        s_nv = acc;
        g_nv[b] = acc;
        float t[8] = {0, 0, 0, 0, 0, 0, 0, 0};
        for (int w = 0; w < 8; w++)
            for (int k = 0; k < 8; k++) t[k] += s_red[w][k];
        g_hdrS[b][0] = pack2(t[0], t[1]);
        g_hdrS[b][1] = pack2(t[2], t[3]);
        g_hdrS[b][2] = pack2(t[4], t[5]);
        g_hdrS[b][3] = pack2(t[6], t[7]);
    }
    __syncthreads();

    // write compacted columns
    int pos = s_wbase[warp] + inc - cnt;
#pragma unroll
    for (int i = 0; i < 4; i++) {
        if (m[i]) {
            ulonglong2 qa, qb;
            qa.x = pack2(X[i][0], Y[i][0]);
            qa.y = pack2(X[i][1], Y[i][1]);
            qb.x = pack2(X[i][2], Y[i][2]);
            qb.y = pack2(SQX[i], SQY[i]);
            g_colA[b][pos] = qa;
            g_colB[b][pos] = qb;
            pos++;
        }
    }
    // zero-fill tail so padded rows are benign
    ulonglong2 z; z.x = 0ULL; z.y = 0ULL;
    for (int k = s_nv + tid; k < LN; k += THREADS) {
        g_colA[b][k] = z;
        g_colB[b][k] = z;
    }
}

// ---------- pair kernel: dense compacted cross-term ----------
__global__ __launch_bounds__(THREADS, 3)
void pair_kernel() {
    const int b = blockIdx.x, tile = blockIdx.y, tid = threadIdx.x;

    __shared__ ulonglong2 sA[LN];
    __shared__ ulonglong2 sB[LN];
    __shared__ float wsum[8];

    const int nv = g_nv[b];
    if (tile * ROWS_PER_CTA >= nv) {
        if (tid == 0) g_part[b * TILES + tile] = 0.0f;
        return;
    }

    for (int i = tid; i < LN; i += THREADS) {
        sA[i] = g_colA[b][i];
        sB[i] = g_colB[b][i];
    }
    __syncthreads();

    const u64 S0 = g_hdrS[b][0], S1 = g_hdrS[b][1], S2 = g_hdrS[b][2], SQ = g_hdrS[b][3];
    const u64 NV2 = pack2((float)nv, (float)nv);

    const int cg = tid & (NCG - 1);
    const int rg = tid >> 4;
    const int row0 = tile * ROWS_PER_CTA + rg * RPT;

    u64 a0[RPT], a1[RPT], a2[RPT], cr[RPT];
    float crTot[RPT], accS[RPT];
#pragma unroll
    for (int r = 0; r < RPT; r++) {
        ulonglong2 qA = sA[row0 + r];
        ulonglong2 qB = sB[row0 + r];
        a0[r] = mul2(qA.x, NEG2_PACKED);
        a1[r] = mul2(qA.y, NEG2_PACKED);
        a2[r] = mul2(qB.x, NEG2_PACKED);
        cr[r] = qB.y;
        // closed form: Sum_j d2(i,j) = nv*sq_i + Sum_j sq_j - 2 * p_i . Sum_j p_j   (packed x/y)
        u64 dot = fma2(qA.x, S0, fma2(qA.y, S1, mul2(qB.x, S2)));
        u64 Cr  = fma2(dot, NEG2_PACKED, fma2(cr[r], NV2, SQ));
        float2 c = unpack2(Cr);
        crTot[r] = c.x + c.y;
        accS[r]  = 0.0f;
    }

#pragma unroll 2
    for (int k = cg; k < nv; k += NCG) {
        ulonglong2 qA = sA[k];
        ulonglong2 qB = sB[k];
#pragma unroll
        for (int r = 0; r < RPT; r++) {
            u64 t = fma2(a0[r], qA.x, cr[r]);
            t = fma2(a1[r], qA.y, t);
            t = fma2(a2[r], qB.x, t);
            t = add2(t, qB.y);
            float2 d = unpack2(t);               // (d2x, d2y)
            float prod = fmaxf(d.x * d.y, 0.0f); // relu'd cross product
            accS[r] += fast_sqrt(prod);          // dx*dy
        }
    }

    // FIX (R2 bug): the closed-form full-row term crTot[r] must be added
    // exactly ONCE per row, not once per column-group thread. Only cg==0
    // contributes it; every thread contributes its partitioned cross term.
    float tsum = 0.0f;
#pragma unroll
    for (int r = 0; r < RPT; r++) {
        if (row0 + r < nv) {
            tsum -= 2.0f * accS[r];
            if (cg == 0) tsum += crTot[r];
        }
    }

    // deterministic block reduce
#pragma unroll
    for (int o = 16; o > 0; o >>= 1)
        tsum += __shfl_down_sync(0xffffffffu, tsum, o);
    if ((tid & 31) == 0) wsum[tid >> 5] = tsum;
    __syncthreads();
    if (tid < 32) {
        float v = (tid < 8) ? wsum[tid] : 0.0f;
#pragma unroll
        for (int o = 4; o > 0; o >>= 1)
            v += __shfl_down_sync(0xffffffffu, v, o);
        if (tid == 0) g_part[b * TILES + tile] = v;
    }
}

// ---------- final kernel ----------
__global__ void final_kernel(float* __restrict__ out) {
    const int tid = threadIdx.x;  // 64 threads
    __shared__ float sh[2];
    float v = 0.0f;
    if (tid < BATCH) {
        float s = 0.0f;
        for (int t = 0; t < TILES; t++) s += g_part[tid * TILES + t];
        v = fast_sqrt(fmaxf(s, 0.0f));
    }
#pragma unroll
    for (int o = 16; o > 0; o >>= 1)
        v += __shfl_down_sync(0xffffffffu, v, o);
    if ((tid & 31) == 0) sh[tid >> 5] = v;
    __syncthreads();
    if (tid == 0) {
        const float denom = 723.3699523f;  // sqrt(1024^2/2 - 1024)
        out[0] = (sh[0] + sh[1]) / denom / (float)BATCH;
    }
}

extern "C" void kernel_launch(void* const* d_in, const int* in_sizes, int n_in,
                              void* d_out, int out_size) {
    const float* x = (const float*)d_in[0];
    const float* y = (const float*)d_in[1];
    float* out = (float*)d_out;
    (void)in_sizes; (void)n_in; (void)out_size;

    pre_kernel<<<BATCH, THREADS>>>(x, y);
    dim3 grid(BATCH, TILES);
    pair_kernel<<<grid, THREADS>>>();
    final_kernel<<<1, 64>>>(out);
}